// round 1
// baseline (speedup 1.0000x reference)
#include <cuda_runtime.h>
#include <math.h>

#define CC   768
#define NH   12
#define DH   64
#define NMTOK 4096
#define NXTOK 16384
#define BB   2
#define MQ   (NXTOK*BB)   // 32768
#define MM   (NMTOK*BB)   // 8192
#define EPSF 1e-6f

// ---------------- scratch (static device arrays; allocation-free) ----------------
__device__ float g_q[(size_t)MQ*CC];          // q -> processed q -> pre-proj buffer
__device__ float g_k[(size_t)MM*CC];          // k -> processed k
__device__ float g_v[(size_t)MM*CC];          // raw v
__device__ float g_dwc[(size_t)MM*CC];        // depthwise conv output, rows (nm*B+b)
__device__ float g_kv[BB*NH*DH*DH];           // 24 x 64x64
__device__ float g_kvp[8*BB*NH*DH*DH];        // split-K partials
__device__ float g_kmean[BB*NH*DH];
__device__ float g_sps[CC];                   // softplus(scale)

// ---------------- softplus of scale ----------------
__global__ void sps_kernel(const float* __restrict__ scale) {
    int c = blockIdx.x * blockDim.x + threadIdx.x;
    if (c < CC) {
        float x = scale[c];
        g_sps[c] = (x > 20.f) ? x : log1pf(expf(x));
    }
}

// ---------------- SGEMM NT: C[M,N] = A[M,K] @ B[N,K]^T (+bias) ----------------
// 128x128 tile, BK=16, 256 threads, 8x8 per thread. M%128==0, N%128==0, K%16==0.
template<bool WITH_BIAS>
__global__ void __launch_bounds__(256, 2) sgemm_nt(
    const float* __restrict__ A, const float* __restrict__ Bm,
    const float* __restrict__ bias, float* __restrict__ Co,
    int M, int N, int K)
{
    __shared__ float As[16][128];
    __shared__ float Bs[16][128];
    const int tid  = threadIdx.x;
    const int row0 = blockIdx.y * 128;
    const int col0 = blockIdx.x * 128;
    const int tx = tid & 15, ty = tid >> 4;
    const int lrow = tid >> 2;          // 0..63
    const int lk   = (tid & 3) << 2;    // 0,4,8,12

    float acc[8][8];
#pragma unroll
    for (int i = 0; i < 8; i++)
#pragma unroll
        for (int j = 0; j < 8; j++) acc[i][j] = 0.f;

    const float* Aptr = A  + (size_t)(row0 + lrow) * K + lk;
    const float* Bptr = Bm + (size_t)(col0 + lrow) * K + lk;

    for (int kt = 0; kt < K; kt += 16) {
#pragma unroll
        for (int p = 0; p < 2; p++) {
            float4 av = *reinterpret_cast<const float4*>(Aptr + (size_t)p * 64 * K + kt);
            As[lk+0][lrow + p*64] = av.x; As[lk+1][lrow + p*64] = av.y;
            As[lk+2][lrow + p*64] = av.z; As[lk+3][lrow + p*64] = av.w;
            float4 bv = *reinterpret_cast<const float4*>(Bptr + (size_t)p * 64 * K + kt);
            Bs[lk+0][lrow + p*64] = bv.x; Bs[lk+1][lrow + p*64] = bv.y;
            Bs[lk+2][lrow + p*64] = bv.z; Bs[lk+3][lrow + p*64] = bv.w;
        }
        __syncthreads();
#pragma unroll
        for (int kk = 0; kk < 16; kk++) {
            float4 a0 = *reinterpret_cast<float4*>(&As[kk][ty*8]);
            float4 a1 = *reinterpret_cast<float4*>(&As[kk][ty*8 + 4]);
            float4 b0 = *reinterpret_cast<float4*>(&Bs[kk][tx*8]);
            float4 b1 = *reinterpret_cast<float4*>(&Bs[kk][tx*8 + 4]);
            float af[8] = {a0.x,a0.y,a0.z,a0.w,a1.x,a1.y,a1.z,a1.w};
            float bf[8] = {b0.x,b0.y,b0.z,b0.w,b1.x,b1.y,b1.z,b1.w};
#pragma unroll
            for (int i = 0; i < 8; i++)
#pragma unroll
                for (int j = 0; j < 8; j++)
                    acc[i][j] += af[i] * bf[j];
        }
        __syncthreads();
    }

#pragma unroll
    for (int i = 0; i < 8; i++) {
        size_t r = (size_t)(row0 + ty*8 + i);
        int cbase = col0 + tx*8;
        float4 v0, v1;
        v0.x = acc[i][0]; v0.y = acc[i][1]; v0.z = acc[i][2]; v0.w = acc[i][3];
        v1.x = acc[i][4]; v1.y = acc[i][5]; v1.z = acc[i][6]; v1.w = acc[i][7];
        if (WITH_BIAS) {
            v0.x += bias[cbase+0]; v0.y += bias[cbase+1];
            v0.z += bias[cbase+2]; v0.w += bias[cbase+3];
            v1.x += bias[cbase+4]; v1.y += bias[cbase+5];
            v1.z += bias[cbase+6]; v1.w += bias[cbase+7];
        }
        *reinterpret_cast<float4*>(&Co[r*N + cbase])     = v0;
        *reinterpret_cast<float4*>(&Co[r*N + cbase + 4]) = v1;
    }
}

// ---------------- focusing feature map, per row over full C ----------------
// t = relu(x)+eps; t /= softplus(scale); out = t^3 * sqrt(sum t^2 / sum t^6)
__global__ void __launch_bounds__(256) process_kernel(float* __restrict__ buf)
{
    const int row = blockIdx.x;
    float* p = buf + (size_t)row * CC;
    const int tid = threadIdx.x;
    float t[3];
    float s2 = 0.f, s6 = 0.f;
#pragma unroll
    for (int u = 0; u < 3; u++) {
        int c = tid + u * 256;
        float v = fmaxf(p[c], 0.f) + EPSF;
        v = v / g_sps[c];
        t[u] = v;
        float v2 = v * v, v3 = v2 * v;
        s2 += v2;
        s6 += v3 * v3;
    }
    __shared__ float r2[256], r6[256];
    r2[tid] = s2; r6[tid] = s6;
    __syncthreads();
    for (int off = 128; off > 0; off >>= 1) {
        if (tid < off) { r2[tid] += r2[tid + off]; r6[tid] += r6[tid + off]; }
        __syncthreads();
    }
    float fac = sqrtf(r2[0] / r6[0]);
#pragma unroll
    for (int u = 0; u < 3; u++) {
        int c = tid + u * 256;
        float v = t[u];
        p[c] = v * v * v * fac;
    }
}

// ---------------- k mean over Nm, per (b,h) ----------------
__global__ void __launch_bounds__(256) kmean_kernel()
{
    int bh = blockIdx.x;                 // 0..23
    int b = bh / NH, h = bh % NH;
    int dd = threadIdx.x & 63, nl = threadIdx.x >> 6;
    float s = 0.f;
    for (int n = nl; n < NMTOK; n += 4)
        s += g_k[((size_t)(n * BB + b)) * CC + h * 64 + dd];
    __shared__ float red[256];
    red[threadIdx.x] = s;
    __syncthreads();
    if (nl == 0)
        g_kmean[bh * 64 + dd] =
            (red[dd] + red[64 + dd] + red[128 + dd] + red[192 + dd]) * (1.f / NMTOK);
}

// ---------------- kv = (1/Nm) k^T v per (b,h), split-K x8 ----------------
__global__ void __launch_bounds__(256) kv_partial()
{
    int bh = blockIdx.x;                 // 0..23
    int b = bh / NH, h = bh % NH;
    int split = blockIdx.y;              // 0..7
    __shared__ float ks[32][64], vs[32][64];
    int tid = threadIdx.x;
    int ti = tid >> 4, tj = tid & 15;
    float acc[4][4];
#pragma unroll
    for (int i = 0; i < 4; i++)
#pragma unroll
        for (int j = 0; j < 4; j++) acc[i][j] = 0.f;

    for (int n0 = split * 512; n0 < split * 512 + 512; n0 += 32) {
        for (int idx = tid; idx < 2048; idx += 256) {
            int nl = idx >> 6, dd = idx & 63;
            size_t g = ((size_t)((n0 + nl) * BB + b)) * CC + h * 64 + dd;
            ks[nl][dd] = g_k[g];
            vs[nl][dd] = g_v[g];
        }
        __syncthreads();
#pragma unroll
        for (int kk = 0; kk < 32; kk++) {
            float4 a  = *reinterpret_cast<float4*>(&ks[kk][ti * 4]);
            float4 c4 = *reinterpret_cast<float4*>(&vs[kk][tj * 4]);
            float af[4] = {a.x, a.y, a.z, a.w};
            float bf[4] = {c4.x, c4.y, c4.z, c4.w};
#pragma unroll
            for (int i = 0; i < 4; i++)
#pragma unroll
                for (int j = 0; j < 4; j++)
                    acc[i][j] += af[i] * bf[j];
        }
        __syncthreads();
    }
    float* o = g_kvp + ((size_t)split * (BB * NH) + bh) * 4096;
    const float inv = 1.f / NMTOK;
#pragma unroll
    for (int i = 0; i < 4; i++)
#pragma unroll
        for (int j = 0; j < 4; j++)
            o[(ti * 4 + i) * 64 + tj * 4 + j] = acc[i][j] * inv;
}

__global__ void kv_reduce()
{
    int idx = blockIdx.x * 256 + threadIdx.x;
    if (idx < BB * NH * 4096) {
        float s = 0.f;
#pragma unroll
        for (int sp = 0; sp < 8; sp++)
            s += g_kvp[(size_t)sp * BB * NH * 4096 + idx];
        g_kv[idx] = s;
    }
}

// ---------------- depthwise 5x5 conv on v over (H=16, W*T=256) grid ----------------
// grid: (colchunk 16, cgroup 48, b 2); 16 channels x 16 cols x 16 rows per block
__global__ void __launch_bounds__(256) dwconv_kernel(
    const float* __restrict__ w, const float* __restrict__ bias)
{
    const int col0 = blockIdx.x * 16;
    const int cg   = blockIdx.y;       // 0..47 -> channels cg*16..+15
    const int b    = blockIdx.z;
    __shared__ float ts[16][20][16];   // [row][col+halo][ch]
    __shared__ float ws[16][25];
    __shared__ float wb[16];
    int tid = threadIdx.x;

    for (int idx = tid; idx < 16 * 20 * 16; idx += 256) {
        int cc = idx & 15;
        int t2 = idx >> 4;
        int colh = t2 % 20;
        int rr = t2 / 20;
        int col = col0 + colh - 2;
        float v = 0.f;
        if (col >= 0 && col < 256)
            v = g_v[((size_t)((rr * 256 + col) * BB + b)) * CC + cg * 16 + cc];
        ts[rr][colh][cc] = v;
    }
    int dd0 = (cg & 3) * 16;           // channel-within-head base (16 | 64)
    for (int idx = tid; idx < 400; idx += 256) {
        int cc = idx / 25, k = idx % 25;
        ws[cc][k] = w[(dd0 + cc) * 25 + k];
    }
    if (tid < 16) wb[tid] = bias[dd0 + tid];
    __syncthreads();

    int cc = tid & 15, cl = tid >> 4;  // cl 0..15 = local col
    for (int rr = 0; rr < 16; rr++) {
        float s = wb[cc];
#pragma unroll
        for (int ki = 0; ki < 5; ki++) {
            int rrr = rr + ki - 2;
            if (rrr >= 0 && rrr < 16) {
#pragma unroll
                for (int kj = 0; kj < 5; kj++)
                    s += ts[rrr][cl + kj][cc] * ws[cc][ki * 5 + kj];
            }
        }
        int n = rr * 256 + col0 + cl;
        g_dwc[((size_t)(n * BB + b)) * CC + cg * 16 + cc] = s;
    }
}

// ---------------- out = (q @ kv) * z + dwc, per (b,h), in place into g_q ----------------
// grid: (Nx/64, heads, B); 64 token-rows x 64 head-channels per block
__global__ void __launch_bounds__(256) attn_out_kernel()
{
    const int h  = blockIdx.y;
    const int b  = blockIdx.z;
    const int n0 = blockIdx.x * 64;
    __shared__ float qs[64][65];
    __shared__ float kvs[64][64];
    __shared__ float kmn[64];
    __shared__ float zrow[64];
    __shared__ float zp[64][4];
    int tid = threadIdx.x;

    for (int idx = tid; idx < 4096; idx += 256) {
        int r = idx >> 6, c = idx & 63;
        qs[r][c] = g_q[((size_t)((n0 + r) * BB + b)) * CC + h * 64 + c];
    }
    for (int idx = tid; idx < 4096; idx += 256)
        kvs[idx >> 6][idx & 63] = g_kv[((size_t)(b * NH + h)) * 4096 + idx];
    if (tid < 64) kmn[tid] = g_kmean[(b * NH + h) * 64 + tid];
    __syncthreads();

    {   // z = 1/(q . k_mean + eps), 4 threads per row
        int r = tid >> 2, l4 = tid & 3;
        float s = 0.f;
        for (int i = l4; i < 64; i += 4) s += qs[r][i] * kmn[i];
        zp[r][l4] = s;
        __syncthreads();
        if (l4 == 0)
            zrow[r] = 1.f / (zp[r][0] + zp[r][1] + zp[r][2] + zp[r][3] + EPSF);
        __syncthreads();
    }

    int tc = tid & 15, tr = tid >> 4;
    float acc[4][4];
#pragma unroll
    for (int i = 0; i < 4; i++)
#pragma unroll
        for (int j = 0; j < 4; j++) acc[i][j] = 0.f;
#pragma unroll
    for (int kk = 0; kk < 64; kk++) {
        float a0 = qs[tr][kk], a1 = qs[tr + 16][kk];
        float a2 = qs[tr + 32][kk], a3 = qs[tr + 48][kk];
        float4 bv = *reinterpret_cast<float4*>(&kvs[kk][tc * 4]);
        acc[0][0] += a0 * bv.x; acc[0][1] += a0 * bv.y; acc[0][2] += a0 * bv.z; acc[0][3] += a0 * bv.w;
        acc[1][0] += a1 * bv.x; acc[1][1] += a1 * bv.y; acc[1][2] += a1 * bv.z; acc[1][3] += a1 * bv.w;
        acc[2][0] += a2 * bv.x; acc[2][1] += a2 * bv.y; acc[2][2] += a2 * bv.z; acc[2][3] += a2 * bv.w;
        acc[3][0] += a3 * bv.x; acc[3][1] += a3 * bv.y; acc[3][2] += a3 * bv.z; acc[3][3] += a3 * bv.w;
    }

#pragma unroll
    for (int i = 0; i < 4; i++) {
        int r  = tr + 16 * i;
        int n  = n0 + r;
        int nm = n & (NMTOK - 1);
        float z = zrow[r];
        size_t qbase = ((size_t)(n  * BB + b)) * CC + h * 64;
        size_t dbase = ((size_t)(nm * BB + b)) * CC + h * 64;
#pragma unroll
        for (int j = 0; j < 4; j++) {
            int c = tc * 4 + j;
            g_q[qbase + c] = acc[i][j] * z + g_dwc[dbase + c];
        }
    }
}

// ---------------- launch ----------------
extern "C" void kernel_launch(void* const* d_in, const int* in_sizes, int n_in,
                              void* d_out, int out_size)
{
    const float* x      = (const float*)d_in[0];
    const float* mem    = (const float*)d_in[1];
    const float* w_q    = (const float*)d_in[2];
    const float* w_k    = (const float*)d_in[3];
    const float* w_v    = (const float*)d_in[4];
    const float* w_proj = (const float*)d_in[5];
    const float* b_proj = (const float*)d_in[6];
    const float* dwc_w  = (const float*)d_in[7];
    const float* dwc_b  = (const float*)d_in[8];
    const float* scale  = (const float*)d_in[9];
    float* out = (float*)d_out;

    float *qp, *kp, *vp;
    cudaGetSymbolAddress((void**)&qp, g_q);
    cudaGetSymbolAddress((void**)&kp, g_k);
    cudaGetSymbolAddress((void**)&vp, g_v);

    sps_kernel<<<3, 256>>>(scale);

    sgemm_nt<false><<<dim3(6, 256), 256>>>(x,   w_q, nullptr, qp, MQ, CC, CC);
    sgemm_nt<false><<<dim3(6, 64),  256>>>(mem, w_k, nullptr, kp, MM, CC, CC);
    sgemm_nt<false><<<dim3(6, 64),  256>>>(mem, w_v, nullptr, vp, MM, CC, CC);

    process_kernel<<<MQ, 256>>>(qp);
    process_kernel<<<MM, 256>>>(kp);

    kmean_kernel<<<24, 256>>>();
    kv_partial<<<dim3(24, 8), 256>>>();
    kv_reduce<<<384, 256>>>();

    dwconv_kernel<<<dim3(16, 48, 2), 256>>>(dwc_w, dwc_b);
    attn_out_kernel<<<dim3(NXTOK / 64, NH, BB), 256>>>();

    sgemm_nt<true><<<dim3(6, 256), 256>>>(qp, w_proj, b_proj, out, MQ, CC, CC);
}

// round 5
// speedup vs baseline: 1.0582x; 1.0582x over previous
#include <cuda_runtime.h>
#include <math.h>

#define CC   768
#define NH   12
#define DH   64
#define NMTOK 4096
#define NXTOK 16384
#define BB   2
#define MQ   (NXTOK*BB)   // 32768
#define MM   (NMTOK*BB)   // 8192
#define EPSF 1e-6f

// ---------------- scratch (static device arrays; allocation-free) ----------------
__device__ float g_q[(size_t)MQ*CC];          // q -> processed q -> pre-proj buffer
__device__ float g_k[(size_t)MM*CC];          // k -> processed k
__device__ float g_v[(size_t)MM*CC];          // raw v
__device__ float g_dwc[(size_t)MM*CC];        // depthwise conv output, rows (nm*B+b)
__device__ float g_kv[BB*NH*DH*DH];           // 24 x 64x64
__device__ float g_kvp[8*BB*NH*DH*DH];        // split-K partials
__device__ float g_kmean[BB*NH*DH];
__device__ float g_sps[CC];                   // softplus(scale)

// ---------------- packed f32x2 helpers ----------------
__device__ __forceinline__ void fma2(unsigned long long &d, unsigned long long a, unsigned long long b) {
    asm("fma.rn.f32x2 %0, %1, %2, %0;" : "+l"(d) : "l"(a), "l"(b));
}
__device__ __forceinline__ unsigned long long dup2(float v) {
    unsigned long long r;
    asm("mov.b64 %0, {%1, %1};" : "=l"(r) : "f"(v));
    return r;
}
__device__ __forceinline__ float2 unpk(unsigned long long v) {
    float2 f;
    asm("mov.b64 {%0, %1}, %2;" : "=f"(f.x), "=f"(f.y) : "l"(v));
    return f;
}

// ---------------- softplus of scale ----------------
__global__ void sps_kernel(const float* __restrict__ scale) {
    int c = blockIdx.x * blockDim.x + threadIdx.x;
    if (c < CC) {
        float x = scale[c];
        g_sps[c] = (x > 20.f) ? x : log1pf(expf(x));
    }
}

// ---------------- SGEMM NT via packed f32x2: C[M,N] = A[M,K] @ B[N,K]^T (+bias) --------
// 128x128 tile, BK=8, 256 threads, 8x8 per thread (2x2 blocks of 4x4).
// A stored duplicated in smem so packed (a,a) operands load directly as u64 pairs.
// Double-buffered smem, register prefetch. M%128==0, N%128==0, K%8==0.
template<bool WITH_BIAS>
__global__ void __launch_bounds__(256, 2) sgemm_nt(
    const float* __restrict__ A, const float* __restrict__ Bm,
    const float* __restrict__ bias, float* __restrict__ Co,
    int M, int N, int K)
{
    __shared__ float As[2][8][260];   // duplicated: word 2r, 2r+1 hold A[kk][r]
    __shared__ float Bs[2][8][132];

    const int tid  = threadIdx.x;
    const int row0 = blockIdx.y * 128;
    const int col0 = blockIdx.x * 128;
    const int tx = tid & 15, ty = tid >> 4;
    const int lrow = tid >> 1;          // 0..127
    const int lk   = (tid & 1) * 4;     // 0 or 4

    unsigned long long acc[2][4][4];
#pragma unroll
    for (int rb = 0; rb < 2; rb++)
#pragma unroll
        for (int i = 0; i < 4; i++)
#pragma unroll
            for (int c = 0; c < 4; c++) acc[rb][i][c] = 0ull;

    const float* Ap = A  + (size_t)(row0 + lrow) * K + lk;
    const float* Bp = Bm + (size_t)(col0 + lrow) * K + lk;

    float4 pa = *reinterpret_cast<const float4*>(Ap);
    float4 pb = *reinterpret_cast<const float4*>(Bp);

    // store prefetched tile into stage s
    {
        *reinterpret_cast<unsigned long long*>(&As[0][lk+0][2*lrow]) = dup2(pa.x);
        *reinterpret_cast<unsigned long long*>(&As[0][lk+1][2*lrow]) = dup2(pa.y);
        *reinterpret_cast<unsigned long long*>(&As[0][lk+2][2*lrow]) = dup2(pa.z);
        *reinterpret_cast<unsigned long long*>(&As[0][lk+3][2*lrow]) = dup2(pa.w);
        Bs[0][lk+0][lrow] = pb.x; Bs[0][lk+1][lrow] = pb.y;
        Bs[0][lk+2][lrow] = pb.z; Bs[0][lk+3][lrow] = pb.w;
    }
    __syncthreads();

    int s = 0;
    for (int kt = 8; kt <= K; kt += 8) {
        const bool more = (kt < K);
        if (more) {
            pa = *reinterpret_cast<const float4*>(Ap + kt);
            pb = *reinterpret_cast<const float4*>(Bp + kt);
        }
#pragma unroll
        for (int kk = 0; kk < 8; kk++) {
            ulonglong2 a01 = *reinterpret_cast<const ulonglong2*>(&As[s][kk][ty*8]);
            ulonglong2 a23 = *reinterpret_cast<const ulonglong2*>(&As[s][kk][ty*8 + 4]);
            ulonglong2 a45 = *reinterpret_cast<const ulonglong2*>(&As[s][kk][128 + ty*8]);
            ulonglong2 a67 = *reinterpret_cast<const ulonglong2*>(&As[s][kk][128 + ty*8 + 4]);
            ulonglong2 bl  = *reinterpret_cast<const ulonglong2*>(&Bs[s][kk][tx*4]);
            ulonglong2 bh  = *reinterpret_cast<const ulonglong2*>(&Bs[s][kk][64 + tx*4]);
            unsigned long long ar[2][4] = {{a01.x, a01.y, a23.x, a23.y},
                                           {a45.x, a45.y, a67.x, a67.y}};
            unsigned long long bb[4] = {bl.x, bl.y, bh.x, bh.y};
#pragma unroll
            for (int rb = 0; rb < 2; rb++)
#pragma unroll
                for (int i = 0; i < 4; i++)
#pragma unroll
                    for (int c = 0; c < 4; c++)
                        fma2(acc[rb][i][c], ar[rb][i], bb[c]);
        }
        if (more) {
            int n = s ^ 1;
            *reinterpret_cast<unsigned long long*>(&As[n][lk+0][2*lrow]) = dup2(pa.x);
            *reinterpret_cast<unsigned long long*>(&As[n][lk+1][2*lrow]) = dup2(pa.y);
            *reinterpret_cast<unsigned long long*>(&As[n][lk+2][2*lrow]) = dup2(pa.z);
            *reinterpret_cast<unsigned long long*>(&As[n][lk+3][2*lrow]) = dup2(pa.w);
            Bs[n][lk+0][lrow] = pb.x; Bs[n][lk+1][lrow] = pb.y;
            Bs[n][lk+2][lrow] = pb.z; Bs[n][lk+3][lrow] = pb.w;
        }
        __syncthreads();
        s ^= 1;
    }

#pragma unroll
    for (int rb = 0; rb < 2; rb++)
#pragma unroll
        for (int i = 0; i < 4; i++) {
            size_t r = (size_t)(row0 + rb*64 + ty*4 + i);
            int c = col0 + tx*4;
            float2 p0 = unpk(acc[rb][i][0]), p1 = unpk(acc[rb][i][1]);
            float2 p2 = unpk(acc[rb][i][2]), p3 = unpk(acc[rb][i][3]);
            float4 lo = make_float4(p0.x, p0.y, p1.x, p1.y);
            float4 hi = make_float4(p2.x, p2.y, p3.x, p3.y);
            if (WITH_BIAS) {
                float4 b0 = *reinterpret_cast<const float4*>(&bias[c]);
                float4 b1 = *reinterpret_cast<const float4*>(&bias[c + 64]);
                lo.x += b0.x; lo.y += b0.y; lo.z += b0.z; lo.w += b0.w;
                hi.x += b1.x; hi.y += b1.y; hi.z += b1.z; hi.w += b1.w;
            }
            *reinterpret_cast<float4*>(&Co[r*N + c])      = lo;
            *reinterpret_cast<float4*>(&Co[r*N + c + 64]) = hi;
        }
}

// ---------------- focusing feature map, per row over full C ----------------
__global__ void __launch_bounds__(256) process_kernel(float* __restrict__ buf)
{
    const int row = blockIdx.x;
    float* p = buf + (size_t)row * CC;
    const int tid = threadIdx.x;
    float t[3];
    float s2 = 0.f, s6 = 0.f;
#pragma unroll
    for (int u = 0; u < 3; u++) {
        int c = tid + u * 256;
        float v = fmaxf(p[c], 0.f) + EPSF;
        v = v / g_sps[c];
        t[u] = v;
        float v2 = v * v, v3 = v2 * v;
        s2 += v2;
        s6 += v3 * v3;
    }
    __shared__ float r2[256], r6[256];
    r2[tid] = s2; r6[tid] = s6;
    __syncthreads();
    for (int off = 128; off > 0; off >>= 1) {
        if (tid < off) { r2[tid] += r2[tid + off]; r6[tid] += r6[tid + off]; }
        __syncthreads();
    }
    float fac = sqrtf(r2[0] / r6[0]);
#pragma unroll
    for (int u = 0; u < 3; u++) {
        int c = tid + u * 256;
        float v = t[u];
        p[c] = v * v * v * fac;
    }
}

// ---------------- k mean over Nm, per (b,h) ----------------
__global__ void __launch_bounds__(256) kmean_kernel()
{
    int bh = blockIdx.x;                 // 0..23
    int b = bh / NH, h = bh % NH;
    int dd = threadIdx.x & 63, nl = threadIdx.x >> 6;
    float s = 0.f;
    for (int n = nl; n < NMTOK; n += 4)
        s += g_k[((size_t)(n * BB + b)) * CC + h * 64 + dd];
    __shared__ float red[256];
    red[threadIdx.x] = s;
    __syncthreads();
    if (nl == 0)
        g_kmean[bh * 64 + dd] =
            (red[dd] + red[64 + dd] + red[128 + dd] + red[192 + dd]) * (1.f / NMTOK);
}

// ---------------- kv = (1/Nm) k^T v per (b,h), split-K x8 ----------------
__global__ void __launch_bounds__(256) kv_partial()
{
    int bh = blockIdx.x;                 // 0..23
    int b = bh / NH, h = bh % NH;
    int split = blockIdx.y;              // 0..7
    __shared__ float ks[32][64], vs[32][64];
    int tid = threadIdx.x;
    int ti = tid >> 4, tj = tid & 15;
    float acc[4][4];
#pragma unroll
    for (int i = 0; i < 4; i++)
#pragma unroll
        for (int j = 0; j < 4; j++) acc[i][j] = 0.f;

    for (int n0 = split * 512; n0 < split * 512 + 512; n0 += 32) {
        for (int idx = tid; idx < 2048; idx += 256) {
            int nl = idx >> 6, dd = idx & 63;
            size_t g = ((size_t)((n0 + nl) * BB + b)) * CC + h * 64 + dd;
            ks[nl][dd] = g_k[g];
            vs[nl][dd] = g_v[g];
        }
        __syncthreads();
#pragma unroll
        for (int kk = 0; kk < 32; kk++) {
            float4 a  = *reinterpret_cast<float4*>(&ks[kk][ti * 4]);
            float4 c4 = *reinterpret_cast<float4*>(&vs[kk][tj * 4]);
            float af[4] = {a.x, a.y, a.z, a.w};
            float bf[4] = {c4.x, c4.y, c4.z, c4.w};
#pragma unroll
            for (int i = 0; i < 4; i++)
#pragma unroll
                for (int j = 0; j < 4; j++)
                    acc[i][j] += af[i] * bf[j];
        }
        __syncthreads();
    }
    float* o = g_kvp + ((size_t)split * (BB * NH) + bh) * 4096;
    const float inv = 1.f / NMTOK;
#pragma unroll
    for (int i = 0; i < 4; i++)
#pragma unroll
        for (int j = 0; j < 4; j++)
            o[(ti * 4 + i) * 64 + tj * 4 + j] = acc[i][j] * inv;
}

__global__ void kv_reduce()
{
    int idx = blockIdx.x * 256 + threadIdx.x;
    if (idx < BB * NH * 4096) {
        float s = 0.f;
#pragma unroll
        for (int sp = 0; sp < 8; sp++)
            s += g_kvp[(size_t)sp * BB * NH * 4096 + idx];
        g_kv[idx] = s;
    }
}

// ---------------- depthwise 5x5 conv on v over (H=16, W*T=256) grid ----------------
__global__ void __launch_bounds__(256) dwconv_kernel(
    const float* __restrict__ w, const float* __restrict__ bias)
{
    const int col0 = blockIdx.x * 16;
    const int cg   = blockIdx.y;       // 0..47 -> channels cg*16..+15
    const int b    = blockIdx.z;
    __shared__ float ts[16][20][16];   // [row][col+halo][ch]
    __shared__ float ws[16][25];
    __shared__ float wb[16];
    int tid = threadIdx.x;

    for (int idx = tid; idx < 16 * 20 * 16; idx += 256) {
        int cc = idx & 15;
        int t2 = idx >> 4;
        int colh = t2 % 20;
        int rr = t2 / 20;
        int col = col0 + colh - 2;
        float v = 0.f;
        if (col >= 0 && col < 256)
            v = g_v[((size_t)((rr * 256 + col) * BB + b)) * CC + cg * 16 + cc];
        ts[rr][colh][cc] = v;
    }
    int dd0 = (cg & 3) * 16;           // channel-within-head base
    for (int idx = tid; idx < 400; idx += 256) {
        int cc = idx / 25, k = idx % 25;
        ws[cc][k] = w[(dd0 + cc) * 25 + k];
    }
    if (tid < 16) wb[tid] = bias[dd0 + tid];
    __syncthreads();

    int cc = tid & 15, cl = tid >> 4;  // cl 0..15 = local col
    for (int rr = 0; rr < 16; rr++) {
        float s = wb[cc];
#pragma unroll
        for (int ki = 0; ki < 5; ki++) {
            int rrr = rr + ki - 2;
            if (rrr >= 0 && rrr < 16) {
#pragma unroll
                for (int kj = 0; kj < 5; kj++)
                    s += ts[rrr][cl + kj][cc] * ws[cc][ki * 5 + kj];
            }
        }
        int n = rr * 256 + col0 + cl;
        g_dwc[((size_t)(n * BB + b)) * CC + cg * 16 + cc] = s;
    }
}

// ---------------- out = (q @ kv) * z + dwc, per (b,h), in place into g_q ----------------
__global__ void __launch_bounds__(256) attn_out_kernel()
{
    const int h  = blockIdx.y;
    const int b  = blockIdx.z;
    const int n0 = blockIdx.x * 64;
    __shared__ float qs[64][65];
    __shared__ float kvs[64][64];
    __shared__ float kmn[64];
    __shared__ float zrow[64];
    __shared__ float zp[64][4];
    int tid = threadIdx.x;

    for (int idx = tid; idx < 4096; idx += 256) {
        int r = idx >> 6, c = idx & 63;
        qs[r][c] = g_q[((size_t)((n0 + r) * BB + b)) * CC + h * 64 + c];
    }
    for (int idx = tid; idx < 4096; idx += 256)
        kvs[idx >> 6][idx & 63] = g_kv[((size_t)(b * NH + h)) * 4096 + idx];
    if (tid < 64) kmn[tid] = g_kmean[(b * NH + h) * 64 + tid];
    __syncthreads();

    {   // z = 1/(q . k_mean + eps), 4 threads per row
        int r = tid >> 2, l4 = tid & 3;
        float s = 0.f;
        for (int i = l4; i < 64; i += 4) s += qs[r][i] * kmn[i];
        zp[r][l4] = s;
        __syncthreads();
        if (l4 == 0)
            zrow[r] = 1.f / (zp[r][0] + zp[r][1] + zp[r][2] + zp[r][3] + EPSF);
        __syncthreads();
    }

    int tc = tid & 15, tr = tid >> 4;
    float acc[4][4];
#pragma unroll
    for (int i = 0; i < 4; i++)
#pragma unroll
        for (int j = 0; j < 4; j++) acc[i][j] = 0.f;
#pragma unroll
    for (int kk = 0; kk < 64; kk++) {
        float a0 = qs[tr][kk], a1 = qs[tr + 16][kk];
        float a2 = qs[tr + 32][kk], a3 = qs[tr + 48][kk];
        float4 bv = *reinterpret_cast<float4*>(&kvs[kk][tc * 4]);
        acc[0][0] += a0 * bv.x; acc[0][1] += a0 * bv.y; acc[0][2] += a0 * bv.z; acc[0][3] += a0 * bv.w;
        acc[1][0] += a1 * bv.x; acc[1][1] += a1 * bv.y; acc[1][2] += a1 * bv.z; acc[1][3] += a1 * bv.w;
        acc[2][0] += a2 * bv.x; acc[2][1] += a2 * bv.y; acc[2][2] += a2 * bv.z; acc[2][3] += a2 * bv.w;
        acc[3][0] += a3 * bv.x; acc[3][1] += a3 * bv.y; acc[3][2] += a3 * bv.z; acc[3][3] += a3 * bv.w;
    }

#pragma unroll
    for (int i = 0; i < 4; i++) {
        int r  = tr + 16 * i;
        int n  = n0 + r;
        int nm = n & (NMTOK - 1);
        float z = zrow[r];
        size_t qbase = ((size_t)(n  * BB + b)) * CC + h * 64;
        size_t dbase = ((size_t)(nm * BB + b)) * CC + h * 64;
#pragma unroll
        for (int j = 0; j < 4; j++) {
            int c = tc * 4 + j;
            g_q[qbase + c] = acc[i][j] * z + g_dwc[dbase + c];
        }
    }
}

// ---------------- launch ----------------
extern "C" void kernel_launch(void* const* d_in, const int* in_sizes, int n_in,
                              void* d_out, int out_size)
{
    const float* x      = (const float*)d_in[0];
    const float* mem    = (const float*)d_in[1];
    const float* w_q    = (const float*)d_in[2];
    const float* w_k    = (const float*)d_in[3];
    const float* w_v    = (const float*)d_in[4];
    const float* w_proj = (const float*)d_in[5];
    const float* b_proj = (const float*)d_in[6];
    const float* dwc_w  = (const float*)d_in[7];
    const float* dwc_b  = (const float*)d_in[8];
    const float* scale  = (const float*)d_in[9];
    float* out = (float*)d_out;

    float *qp, *kp, *vp;
    cudaGetSymbolAddress((void**)&qp, g_q);
    cudaGetSymbolAddress((void**)&kp, g_k);
    cudaGetSymbolAddress((void**)&vp, g_v);

    sps_kernel<<<3, 256>>>(scale);

    sgemm_nt<false><<<dim3(6, 256), 256>>>(x,   w_q, nullptr, qp, MQ, CC, CC);
    sgemm_nt<false><<<dim3(6, 64),  256>>>(mem, w_k, nullptr, kp, MM, CC, CC);
    sgemm_nt<false><<<dim3(6, 64),  256>>>(mem, w_v, nullptr, vp, MM, CC, CC);

    process_kernel<<<MQ, 256>>>(qp);
    process_kernel<<<MM, 256>>>(kp);

    kmean_kernel<<<24, 256>>>();
    kv_partial<<<dim3(24, 8), 256>>>();
    kv_reduce<<<384, 256>>>();

    dwconv_kernel<<<dim3(16, 48, 2), 256>>>(dwc_w, dwc_b);
    attn_out_kernel<<<dim3(NXTOK / 64, NH, BB), 256>>>();

    sgemm_nt<true><<<dim3(6, 256), 256>>>(qp, w_proj, b_proj, out, MQ, CC, CC);
}

// round 9
// speedup vs baseline: 2.1222x; 2.0055x over previous
#include <cuda_runtime.h>
#include <cuda_bf16.h>
#include <math.h>
#include <cstdint>

#define CC    768
#define NH    12
#define DH    64
#define NMTOK 4096
#define NXTOK 16384
#define BB    2
#define MQ    (NXTOK*BB)   // 32768
#define MM    (NMTOK*BB)   // 8192
#define EPSF  1e-6f

#define GK     2304        // expanded K = 3*768
#define KCH    32          // K per smem chunk (bf16)
#define NCHUNK (GK/KCH)    // 72

// ---------------- scratch (static device arrays; allocation-free) ----------------
__device__ float g_q[(size_t)MQ*CC];              // q fp32 (processed in place)
__device__ float g_k[(size_t)MM*CC];              // k fp32
__device__ float g_v[(size_t)MM*CC];              // v fp32
__device__ float g_dwc[(size_t)MM*CC];            // depthwise conv output
__device__ float g_kv[BB*NH*DH*DH];
__device__ float g_kvp[8*BB*NH*DH*DH];
__device__ float g_kmean[BB*NH*DH];
__device__ float g_sps[CC];
__device__ __nv_bfloat16 g_xp[(size_t)MQ*GK];     // x' triple-split [h|l|h]; later attn-out'
__device__ __nv_bfloat16 g_mp[(size_t)MM*GK];     // mem' triple-split [h|l|h]
__device__ __nv_bfloat16 g_wp[(size_t)4*CC*GK];   // weights' triple-split [h|h|l]

// ---------------- mma.sync / ldmatrix / cp.async helpers (plain sm_103-safe) ----------------
__device__ __forceinline__ void ldmx4(uint32_t* r, uint32_t addr) {
    asm volatile("ldmatrix.sync.aligned.m8n8.x4.shared.b16 {%0,%1,%2,%3}, [%4];"
        : "=r"(r[0]), "=r"(r[1]), "=r"(r[2]), "=r"(r[3]) : "r"(addr));
}
__device__ __forceinline__ void mma16816(float* c, const uint32_t* a, uint32_t b0, uint32_t b1) {
    asm volatile("mma.sync.aligned.m16n8k16.row.col.f32.bf16.bf16.f32 "
        "{%0,%1,%2,%3}, {%4,%5,%6,%7}, {%8,%9}, {%0,%1,%2,%3};"
        : "+f"(c[0]), "+f"(c[1]), "+f"(c[2]), "+f"(c[3])
        : "r"(a[0]), "r"(a[1]), "r"(a[2]), "r"(a[3]), "r"(b0), "r"(b1));
}
__device__ __forceinline__ void cp16(uint32_t dst, const void* src) {
    asm volatile("cp.async.cg.shared.global [%0], [%1], 16;" :: "r"(dst), "l"(src));
}
#define CP_COMMIT() asm volatile("cp.async.commit_group;" ::: "memory")
#define CP_WAIT(N)  asm volatile("cp.async.wait_group %0;" :: "n"(N) : "memory")

// ---------------- bf16 mma GEMM: Co[M, CC] = A'[M,GK] @ B'[CC,GK]^T (+bias) --------------
// 128x128 tile, BK=32, 256 threads (8 warps 2x4), warp tile 64x32 via m16n8k16.
// Smem 16B-chunk XOR swizzle: chunk ^= (row>>1)&3  (conflict-free ldmatrix + stores).
template<bool WITH_BIAS>
__global__ void __launch_bounds__(256, 2) gemm_bf16mma(
    const __nv_bfloat16* __restrict__ A, const __nv_bfloat16* __restrict__ Bw,
    const float* __restrict__ bias, float* __restrict__ Co)
{
    __shared__ __align__(16) char sm[2][16384];   // per stage: A 8KB | B 8KB

    const int tid  = threadIdx.x;
    const int lane = tid & 31;
    const int wid  = tid >> 5;
    const int wm   = wid & 1;        // warp row (64 m-rows each)
    const int wn   = wid >> 1;       // warp col (32 n-cols each)
    const int row0 = blockIdx.y * 128;
    const int col0 = blockIdx.x * 128;

    // global->smem: thread handles rows (lr, lr+64) x chunk lc for both A and B
    const int lr = tid >> 2;         // 0..63
    const int lc = tid & 3;          // 16B chunk (8 bf16)
    const uint32_t dstA0 = (uint32_t)__cvta_generic_to_shared(&sm[0][0]);
    const uint32_t dstB0 = dstA0 + 8192;
    const int swz0 = (lc ^ ((lr >> 1) & 3)) << 4;
    const int swz1 = (lc ^ (((lr + 64) >> 1) & 3)) << 4;

    const __nv_bfloat16* Ap0 = A  + (size_t)(row0 + lr) * GK + lc * 8;
    const __nv_bfloat16* Bp0 = Bw + (size_t)(col0 + lr) * GK + lc * 8;

    // fragment smem addresses (precomputed row parts)
    uint32_t aoff[4]; int asw[4];
    {
        int ar = lane & 15;
        for (int mt = 0; mt < 4; mt++) {
            int r = wm * 64 + mt * 16 + ar;
            aoff[mt] = r * 64;
            asw[mt] = (r >> 1) & 3;
        }
    }
    uint32_t boff[2]; int bsw[2];
    {
        int brr = ((lane >> 4) << 3) + (lane & 7);
        for (int p = 0; p < 2; p++) {
            int r = wn * 32 + p * 16 + brr;
            boff[p] = r * 64;
            bsw[p] = (r >> 1) & 3;
        }
    }
    const int ah = lane >> 4;          // A k-half select
    const int bh = (lane >> 3) & 1;    // B k-half select

    float acc[4][4][4];
#pragma unroll
    for (int mt = 0; mt < 4; mt++)
#pragma unroll
        for (int nt = 0; nt < 4; nt++)
#pragma unroll
            for (int e = 0; e < 4; e++) acc[mt][nt][e] = 0.f;

    // prologue: stage 0
    {
        uint32_t dA = dstA0, dB = dstB0;
        cp16(dA + lr * 64 + swz0,        Ap0);
        cp16(dA + (lr + 64) * 64 + swz1, Ap0 + (size_t)64 * GK);
        cp16(dB + lr * 64 + swz0,        Bp0);
        cp16(dB + (lr + 64) * 64 + swz1, Bp0 + (size_t)64 * GK);
        CP_COMMIT();
    }

    for (int ic = 0; ic < NCHUNK; ic++) {
        const int s = ic & 1;
        if (ic + 1 < NCHUNK) {
            uint32_t dA = dstA0 + (s ^ 1) * 16384;
            uint32_t dB = dA + 8192;
            const __nv_bfloat16* Ap = Ap0 + (ic + 1) * KCH;
            const __nv_bfloat16* Bp = Bp0 + (ic + 1) * KCH;
            cp16(dA + lr * 64 + swz0,        Ap);
            cp16(dA + (lr + 64) * 64 + swz1, Ap + (size_t)64 * GK);
            cp16(dB + lr * 64 + swz0,        Bp);
            cp16(dB + (lr + 64) * 64 + swz1, Bp + (size_t)64 * GK);
            CP_COMMIT();
            CP_WAIT(1);
        } else {
            CP_WAIT(0);
        }
        __syncthreads();

        const uint32_t sA = dstA0 + s * 16384;
        const uint32_t sB = sA + 8192;
#pragma unroll
        for (int kk = 0; kk < 2; kk++) {
            uint32_t afr[4][4], bfr[2][4];
#pragma unroll
            for (int mt = 0; mt < 4; mt++)
                ldmx4(afr[mt], sA + aoff[mt] + (((kk * 2 + ah) ^ asw[mt]) << 4));
#pragma unroll
            for (int p = 0; p < 2; p++)
                ldmx4(bfr[p], sB + boff[p] + (((kk * 2 + bh) ^ bsw[p]) << 4));
#pragma unroll
            for (int mt = 0; mt < 4; mt++) {
                mma16816(acc[mt][0], afr[mt], bfr[0][0], bfr[0][1]);
                mma16816(acc[mt][1], afr[mt], bfr[0][2], bfr[0][3]);
                mma16816(acc[mt][2], afr[mt], bfr[1][0], bfr[1][1]);
                mma16816(acc[mt][3], afr[mt], bfr[1][2], bfr[1][3]);
            }
        }
        __syncthreads();
    }

    // epilogue: C frag (c0,c1)->(r, 2c), (c2,c3)->(r+8, 2c)
    const int l4r = lane >> 2, l4c = lane & 3;
#pragma unroll
    for (int mt = 0; mt < 4; mt++) {
#pragma unroll
        for (int nt = 0; nt < 4; nt++) {
            int r = row0 + wm * 64 + mt * 16 + l4r;
            int c = col0 + wn * 32 + nt * 8 + l4c * 2;
            float2 v0 = make_float2(acc[mt][nt][0], acc[mt][nt][1]);
            float2 v1 = make_float2(acc[mt][nt][2], acc[mt][nt][3]);
            if (WITH_BIAS) {
                float2 bv = *reinterpret_cast<const float2*>(bias + c);
                v0.x += bv.x; v0.y += bv.y;
                v1.x += bv.x; v1.y += bv.y;
            }
            *reinterpret_cast<float2*>(Co + (size_t)r * CC + c)       = v0;
            *reinterpret_cast<float2*>(Co + (size_t)(r + 8) * CC + c) = v1;
        }
    }
}

// ---------------- fp32 -> triple bf16 split ----------------
// AMODE=1 (activations): dst row = [hi | lo | hi]
// AMODE=0 (weights):     dst row = [hi | hi | lo]
// Product [Ah|Al|Ah] . [Bh|Bh|Bl] = AhBh + AlBh + AhBl ~= fp32 A.B
template<int AMODE>
__global__ void __launch_bounds__(256) conv3_kernel(
    const float* __restrict__ src, __nv_bfloat16* __restrict__ dst, int nrows)
{
    size_t idx = (size_t)blockIdx.x * 256 + threadIdx.x;
    size_t total = (size_t)nrows * 192;          // groups of 4 floats
    if (idx >= total) return;
    size_t r = idx / 192;
    int c4 = (int)(idx % 192);
    float4 v = reinterpret_cast<const float4*>(src)[idx];
    __nv_bfloat16 h0 = __float2bfloat16(v.x), h1 = __float2bfloat16(v.y);
    __nv_bfloat16 h2 = __float2bfloat16(v.z), h3 = __float2bfloat16(v.w);
    __nv_bfloat16 l0 = __float2bfloat16(v.x - __bfloat162float(h0));
    __nv_bfloat16 l1 = __float2bfloat16(v.y - __bfloat162float(h1));
    __nv_bfloat16 l2 = __float2bfloat16(v.z - __bfloat162float(h2));
    __nv_bfloat16 l3 = __float2bfloat16(v.w - __bfloat162float(h3));
    __nv_bfloat162 hA = __halves2bfloat162(h0, h1), hB = __halves2bfloat162(h2, h3);
    __nv_bfloat162 lA = __halves2bfloat162(l0, l1), lB = __halves2bfloat162(l2, l3);
    __nv_bfloat16* row = dst + r * GK + c4 * 4;
    reinterpret_cast<__nv_bfloat162*>(row)[0] = hA;
    reinterpret_cast<__nv_bfloat162*>(row)[1] = hB;
    if (AMODE) {   // [h | l | h]
        reinterpret_cast<__nv_bfloat162*>(row + 768)[0] = lA;
        reinterpret_cast<__nv_bfloat162*>(row + 768)[1] = lB;
        reinterpret_cast<__nv_bfloat162*>(row + 1536)[0] = hA;
        reinterpret_cast<__nv_bfloat162*>(row + 1536)[1] = hB;
    } else {       // [h | h | l]
        reinterpret_cast<__nv_bfloat162*>(row + 768)[0] = hA;
        reinterpret_cast<__nv_bfloat162*>(row + 768)[1] = hB;
        reinterpret_cast<__nv_bfloat162*>(row + 1536)[0] = lA;
        reinterpret_cast<__nv_bfloat162*>(row + 1536)[1] = lB;
    }
}

// ---------------- softplus of scale ----------------
__global__ void sps_kernel(const float* __restrict__ scale) {
    int c = blockIdx.x * blockDim.x + threadIdx.x;
    if (c < CC) {
        float x = scale[c];
        g_sps[c] = (x > 20.f) ? x : log1pf(expf(x));
    }
}

// ---------------- focusing feature map, per row over full C ----------------
__global__ void __launch_bounds__(256) process_kernel(float* __restrict__ buf)
{
    const int row = blockIdx.x;
    float* p = buf + (size_t)row * CC;
    const int tid = threadIdx.x;
    float t[3];
    float s2 = 0.f, s6 = 0.f;
#pragma unroll
    for (int u = 0; u < 3; u++) {
        int c = tid + u * 256;
        float v = fmaxf(p[c], 0.f) + EPSF;
        v = v / g_sps[c];
        t[u] = v;
        float v2 = v * v, v3 = v2 * v;
        s2 += v2;
        s6 += v3 * v3;
    }
    __shared__ float r2[256], r6[256];
    r2[tid] = s2; r6[tid] = s6;
    __syncthreads();
    for (int off = 128; off > 0; off >>= 1) {
        if (tid < off) { r2[tid] += r2[tid + off]; r6[tid] += r6[tid + off]; }
        __syncthreads();
    }
    float fac = sqrtf(r2[0] / r6[0]);
#pragma unroll
    for (int u = 0; u < 3; u++) {
        int c = tid + u * 256;
        float v = t[u];
        p[c] = v * v * v * fac;
    }
}

// ---------------- k mean over Nm, per (b,h) ----------------
__global__ void __launch_bounds__(256) kmean_kernel()
{
    int bh = blockIdx.x;
    int b = bh / NH, h = bh % NH;
    int dd = threadIdx.x & 63, nl = threadIdx.x >> 6;
    float s = 0.f;
    for (int n = nl; n < NMTOK; n += 4)
        s += g_k[((size_t)(n * BB + b)) * CC + h * 64 + dd];
    __shared__ float red[256];
    red[threadIdx.x] = s;
    __syncthreads();
    if (nl == 0)
        g_kmean[bh * 64 + dd] =
            (red[dd] + red[64 + dd] + red[128 + dd] + red[192 + dd]) * (1.f / NMTOK);
}

// ---------------- kv = (1/Nm) k^T v per (b,h), split-K x8 ----------------
__global__ void __launch_bounds__(256) kv_partial()
{
    int bh = blockIdx.x;
    int b = bh / NH, h = bh % NH;
    int split = blockIdx.y;
    __shared__ float ks[32][64], vs[32][64];
    int tid = threadIdx.x;
    int ti = tid >> 4, tj = tid & 15;
    float acc[4][4];
#pragma unroll
    for (int i = 0; i < 4; i++)
#pragma unroll
        for (int j = 0; j < 4; j++) acc[i][j] = 0.f;

    for (int n0 = split * 512; n0 < split * 512 + 512; n0 += 32) {
        for (int idx = tid; idx < 2048; idx += 256) {
            int nl = idx >> 6, dd = idx & 63;
            size_t g = ((size_t)((n0 + nl) * BB + b)) * CC + h * 64 + dd;
            ks[nl][dd] = g_k[g];
            vs[nl][dd] = g_v[g];
        }
        __syncthreads();
#pragma unroll
        for (int kk = 0; kk < 32; kk++) {
            float4 a  = *reinterpret_cast<float4*>(&ks[kk][ti * 4]);
            float4 c4 = *reinterpret_cast<float4*>(&vs[kk][tj * 4]);
            float af[4] = {a.x, a.y, a.z, a.w};
            float bf[4] = {c4.x, c4.y, c4.z, c4.w};
#pragma unroll
            for (int i = 0; i < 4; i++)
#pragma unroll
                for (int j = 0; j < 4; j++)
                    acc[i][j] += af[i] * bf[j];
        }
        __syncthreads();
    }
    float* o = g_kvp + ((size_t)split * (BB * NH) + bh) * 4096;
    const float inv = 1.f / NMTOK;
#pragma unroll
    for (int i = 0; i < 4; i++)
#pragma unroll
        for (int j = 0; j < 4; j++)
            o[(ti * 4 + i) * 64 + tj * 4 + j] = acc[i][j] * inv;
}

__global__ void kv_reduce()
{
    int idx = blockIdx.x * 256 + threadIdx.x;
    if (idx < BB * NH * 4096) {
        float s = 0.f;
#pragma unroll
        for (int sp = 0; sp < 8; sp++)
            s += g_kvp[(size_t)sp * BB * NH * 4096 + idx];
        g_kv[idx] = s;
    }
}

// ---------------- depthwise 5x5 conv on v over (H=16, W*T=256) grid ----------------
__global__ void __launch_bounds__(256) dwconv_kernel(
    const float* __restrict__ w, const float* __restrict__ bias)
{
    const int col0 = blockIdx.x * 16;
    const int cg   = blockIdx.y;
    const int b    = blockIdx.z;
    __shared__ float ts[16][20][16];
    __shared__ float ws[16][25];
    __shared__ float wb[16];
    int tid = threadIdx.x;

    for (int idx = tid; idx < 16 * 20 * 16; idx += 256) {
        int cc = idx & 15;
        int t2 = idx >> 4;
        int colh = t2 % 20;
        int rr = t2 / 20;
        int col = col0 + colh - 2;
        float v = 0.f;
        if (col >= 0 && col < 256)
            v = g_v[((size_t)((rr * 256 + col) * BB + b)) * CC + cg * 16 + cc];
        ts[rr][colh][cc] = v;
    }
    int dd0 = (cg & 3) * 16;
    for (int idx = tid; idx < 400; idx += 256) {
        int cc = idx / 25, k = idx % 25;
        ws[cc][k] = w[(dd0 + cc) * 25 + k];
    }
    if (tid < 16) wb[tid] = bias[dd0 + tid];
    __syncthreads();

    int cc = tid & 15, cl = tid >> 4;
    for (int rr = 0; rr < 16; rr++) {
        float s = wb[cc];
#pragma unroll
        for (int ki = 0; ki < 5; ki++) {
            int rrr = rr + ki - 2;
            if (rrr >= 0 && rrr < 16) {
#pragma unroll
                for (int kj = 0; kj < 5; kj++)
                    s += ts[rrr][cl + kj][cc] * ws[cc][ki * 5 + kj];
            }
        }
        int n = rr * 256 + col0 + cl;
        g_dwc[((size_t)(n * BB + b)) * CC + cg * 16 + cc] = s;
    }
}

// ---------------- out = (q @ kv) * z + dwc -> write bf16 triple split [h|l|h] into g_xp ----
__global__ void __launch_bounds__(256) attn_out_kernel()
{
    const int h  = blockIdx.y;
    const int b  = blockIdx.z;
    const int n0 = blockIdx.x * 64;
    __shared__ float qs[64][65];
    __shared__ float kvs[64][64];
    __shared__ float kmn[64];
    __shared__ float zrow[64];
    __shared__ float zp[64][4];
    int tid = threadIdx.x;

    for (int idx = tid; idx < 4096; idx += 256) {
        int r = idx >> 6, c = idx & 63;
        qs[r][c] = g_q[((size_t)((n0 + r) * BB + b)) * CC + h * 64 + c];
    }
    for (int idx = tid; idx < 4096; idx += 256)
        kvs[idx >> 6][idx & 63] = g_kv[((size_t)(b * NH + h)) * 4096 + idx];
    if (tid < 64) kmn[tid] = g_kmean[(b * NH + h) * 64 + tid];
    __syncthreads();

    {
        int r = tid >> 2, l4 = tid & 3;
        float s = 0.f;
        for (int i = l4; i < 64; i += 4) s += qs[r][i] * kmn[i];
        zp[r][l4] = s;
        __syncthreads();
        if (l4 == 0)
            zrow[r] = 1.f / (zp[r][0] + zp[r][1] + zp[r][2] + zp[r][3] + EPSF);
        __syncthreads();
    }

    int tc = tid & 15, tr = tid >> 4;
    float acc[4][4];
#pragma unroll
    for (int i = 0; i < 4; i++)
#pragma unroll
        for (int j = 0; j < 4; j++) acc[i][j] = 0.f;
#pragma unroll
    for (int kk = 0; kk < 64; kk++) {
        float a0 = qs[tr][kk], a1 = qs[tr + 16][kk];
        float a2 = qs[tr + 32][kk], a3 = qs[tr + 48][kk];
        float4 bv = *reinterpret_cast<float4*>(&kvs[kk][tc * 4]);
        acc[0][0] += a0 * bv.x; acc[0][1] += a0 * bv.y; acc[0][2] += a0 * bv.z; acc[0][3] += a0 * bv.w;
        acc[1][0] += a1 * bv.x; acc[1][1] += a1 * bv.y; acc[1][2] += a1 * bv.z; acc[1][3] += a1 * bv.w;
        acc[2][0] += a2 * bv.x; acc[2][1] += a2 * bv.y; acc[2][2] += a2 * bv.z; acc[2][3] += a2 * bv.w;
        acc[3][0] += a3 * bv.x; acc[3][1] += a3 * bv.y; acc[3][2] += a3 * bv.z; acc[3][3] += a3 * bv.w;
    }

#pragma unroll
    for (int i = 0; i < 4; i++) {
        int r  = tr + 16 * i;
        int n  = n0 + r;
        int nm = n & (NMTOK - 1);
        float z = zrow[r];
        size_t dbase = ((size_t)(nm * BB + b)) * CC + h * 64;
        __nv_bfloat16* row = g_xp + (size_t)(n * BB + b) * GK + h * 64 + tc * 4;
        float val[4];
#pragma unroll
        for (int j = 0; j < 4; j++)
            val[j] = acc[i][j] * z + g_dwc[dbase + tc * 4 + j];
        __nv_bfloat16 h0 = __float2bfloat16(val[0]), h1 = __float2bfloat16(val[1]);
        __nv_bfloat16 h2 = __float2bfloat16(val[2]), h3 = __float2bfloat16(val[3]);
        __nv_bfloat16 l0 = __float2bfloat16(val[0] - __bfloat162float(h0));
        __nv_bfloat16 l1 = __float2bfloat16(val[1] - __bfloat162float(h1));
        __nv_bfloat16 l2 = __float2bfloat16(val[2] - __bfloat162float(h2));
        __nv_bfloat16 l3 = __float2bfloat16(val[3] - __bfloat162float(h3));
        __nv_bfloat162 hA = __halves2bfloat162(h0, h1), hB = __halves2bfloat162(h2, h3);
        __nv_bfloat162 lA = __halves2bfloat162(l0, l1), lB = __halves2bfloat162(l2, l3);
        reinterpret_cast<__nv_bfloat162*>(row)[0] = hA;
        reinterpret_cast<__nv_bfloat162*>(row)[1] = hB;
        reinterpret_cast<__nv_bfloat162*>(row + 768)[0] = lA;
        reinterpret_cast<__nv_bfloat162*>(row + 768)[1] = lB;
        reinterpret_cast<__nv_bfloat162*>(row + 1536)[0] = hA;
        reinterpret_cast<__nv_bfloat162*>(row + 1536)[1] = hB;
    }
}

// ---------------- launch ----------------
extern "C" void kernel_launch(void* const* d_in, const int* in_sizes, int n_in,
                              void* d_out, int out_size)
{
    const float* x      = (const float*)d_in[0];
    const float* mem    = (const float*)d_in[1];
    const float* w_q    = (const float*)d_in[2];
    const float* w_k    = (const float*)d_in[3];
    const float* w_v    = (const float*)d_in[4];
    const float* w_proj = (const float*)d_in[5];
    const float* b_proj = (const float*)d_in[6];
    const float* dwc_w  = (const float*)d_in[7];
    const float* dwc_b  = (const float*)d_in[8];
    const float* scale  = (const float*)d_in[9];
    float* out = (float*)d_out;

    float *qp, *kp, *vp;
    __nv_bfloat16 *xp, *mp, *wp;
    cudaGetSymbolAddress((void**)&qp, g_q);
    cudaGetSymbolAddress((void**)&kp, g_k);
    cudaGetSymbolAddress((void**)&vp, g_v);
    cudaGetSymbolAddress((void**)&xp, g_xp);
    cudaGetSymbolAddress((void**)&mp, g_mp);
    cudaGetSymbolAddress((void**)&wp, g_wp);

    sps_kernel<<<3, 256>>>(scale);

    // activations: [h|l|h]
    conv3_kernel<1><<<(MQ * 192 + 255) / 256, 256>>>(x, xp, MQ);
    conv3_kernel<1><<<(MM * 192 + 255) / 256, 256>>>(mem, mp, MM);
    // weights: [h|h|l]
    conv3_kernel<0><<<(CC * 192 + 255) / 256, 256>>>(w_q,    wp + (size_t)0 * CC * GK, CC);
    conv3_kernel<0><<<(CC * 192 + 255) / 256, 256>>>(w_k,    wp + (size_t)1 * CC * GK, CC);
    conv3_kernel<0><<<(CC * 192 + 255) / 256, 256>>>(w_v,    wp + (size_t)2 * CC * GK, CC);
    conv3_kernel<0><<<(CC * 192 + 255) / 256, 256>>>(w_proj, wp + (size_t)3 * CC * GK, CC);

    // q/k/v projections via bf16 mma (3xBF16 split)
    gemm_bf16mma<false><<<dim3(6, MQ / 128), 256>>>(xp, wp + (size_t)0 * CC * GK, nullptr, qp);
    gemm_bf16mma<false><<<dim3(6, MM / 128), 256>>>(mp, wp + (size_t)1 * CC * GK, nullptr, kp);
    gemm_bf16mma<false><<<dim3(6, MM / 128), 256>>>(mp, wp + (size_t)2 * CC * GK, nullptr, vp);

    process_kernel<<<MQ, 256>>>(qp);
    process_kernel<<<MM, 256>>>(kp);

    kmean_kernel<<<24, 256>>>();
    kv_partial<<<dim3(24, 8), 256>>>();
    kv_reduce<<<384, 256>>>();

    dwconv_kernel<<<dim3(16, 48, 2), 256>>>(dwc_w, dwc_b);
    attn_out_kernel<<<dim3(NXTOK / 64, NH, BB), 256>>>();

    // final projection with bias
    gemm_bf16mma<true><<<dim3(6, MQ / 128), 256>>>(xp, wp + (size_t)3 * CC * GK, b_proj, out);
}